// round 11
// baseline (speedup 1.0000x reference)
#include <cuda_runtime.h>
#include <cuda_bf16.h>
#include <cstdint>

// CRF forward scan, exp domain. 128 persistent CTAs.
// Fast path: consumers poll their OWN 16B of the bf16 W slot ring with ld.cv
// until no 16-bit half has the sign bit set (canary 0xFFC0). Detect == data
// load: ONE L2 round trip, no pre-dot barrier. Liveness: bounded canary tries
// + release-counter fallback (R9, proven hang-free).
// R10: smem reduce tree replaced by a 16-row warp split-butterfly
// (16 shuffles), leaving ONE __syncthreads per step. red[] parity-buffered.
// Normalizer: lagged sqrt-damped max by warp 1, off the critical path.

#define T 2048
#define ROWS 16
#define NBLK 128
#define NTHR 256
#define DEPTH 8
#define START_IDX 0
#define END_IDX 1
#define CANARY 0xFFC0FFC0u
#define POLL_TRIES 64

__device__ __align__(16) float g_Ef[(size_t)T * T];        // 16 MB exp(transitions)
__device__ __align__(16) unsigned g_W[DEPTH][T / 2];        // bf16-pair slot ring
__device__ unsigned g_cnt;                                  // fallback counter

typedef unsigned long long ull;

__device__ __forceinline__ ull pack2f(float a, float b) {
    ull r; asm("mov.b64 %0, {%1, %2};" : "=l"(r) : "f"(a), "f"(b)); return r;
}
__device__ __forceinline__ ull pack2u(unsigned a, unsigned b) {
    ull r; asm("mov.b64 %0, {%1, %2};" : "=l"(r) : "r"(a), "r"(b)); return r;
}
__device__ __forceinline__ void unpack2f(ull p, float& a, float& b) {
    asm("mov.b64 {%0, %1}, %2;" : "=f"(a), "=f"(b) : "l"(p));
}
#define FMA2(acc, a, b) \
    asm("fma.rn.f32x2 %0, %1, %2, %0;" : "+l"(acc) : "l"(a), "l"(b))

__device__ __forceinline__ uint4 ld16cv(const unsigned* p) {
    uint4 w;
    asm volatile("ld.global.cv.v4.u32 {%0,%1,%2,%3}, [%4];"
                 : "=r"(w.x), "=r"(w.y), "=r"(w.z), "=r"(w.w) : "l"(p));
    return w;
}

// Canary poll with bounded tries + counter fallback. Always terminates.
__device__ __forceinline__ uint4 wait16B(const unsigned* p, unsigned cnt_target) {
    uint4 w;
    #pragma unroll 1
    for (int i = 0; i < POLL_TRIES; i++) {
        w = ld16cv(p);
        if (!((w.x | w.y | w.z | w.w) & 0x80008000u)) return w;
        __nanosleep(32);
    }
    unsigned c;
    do {
        asm volatile("ld.acquire.gpu.global.u32 %0, [%1];" : "=r"(c) : "l"(&g_cnt));
        if (c < cnt_target) __nanosleep(64);
    } while (c < cnt_target);
    return ld16cv(p);
}

__global__ void crf_init(const float* __restrict__ trans) {
    size_t idx = (size_t)blockIdx.x * blockDim.x + threadIdx.x;
    size_t stride = (size_t)gridDim.x * blockDim.x;
    for (size_t i = idx; i < (size_t)T * T; i += stride)
        g_Ef[i] = __expf(trans[i]);
    if (idx < T / 2) {
        g_W[0][idx] = (idx == 0) ? 0x00003F80u : 0u;   // W_0: bf16(1.0) at tag 0
        #pragma unroll
        for (int s = 1; s < DEPTH; s++) g_W[s][idx] = CANARY;
    }
    if (idx == 0) g_cnt = 0u;
}

__global__ void __launch_bounds__(NTHR, 1)
crf_main(const float* __restrict__ h, const float* __restrict__ trans,
         float* __restrict__ out, int S) {
    __shared__ __align__(16) float red[2][8 * ROWS];    // parity warp-partials
    __shared__ __align__(16) float mxs[2][NTHR];        // parity local maxes
    __shared__ float sNorm[2];
    __shared__ double sL;

    const int tid = threadIdx.x;
    const int wid = tid >> 5;
    const int ln = tid & 31;
    const int b = blockIdx.x;
    const int r0 = b * ROWS;
    const int c0 = wid * 256 + ln * 8;    // my 8 columns
    const int wslot = c0 >> 1;            // word offset of my 16B in a slot
    // butterfly output row for this lane: bitrev4(ln&15)
    const int brow = ((ln & 1) << 3) | ((ln & 2) << 1) | ((ln & 4) >> 1) | ((ln & 8) >> 3);

    if (tid == 0) { sNorm[0] = 1.0f; sNorm[1] = 1.0f; }

    // E -> registers: rows r0..r0+15 x my 8 cols, packed f32x2
    ull e64[ROWS][4];
    #pragma unroll
    for (int r = 0; r < ROWS; r++) {
        const float4* ep = (const float4*)(g_Ef + (size_t)(r0 + r) * T + c0);
        float4 a = ep[0], bb = ep[1];
        e64[r][0] = pack2f(a.x, a.y);
        e64[r][1] = pack2f(a.z, a.w);
        e64[r][2] = pack2f(bb.x, bb.y);
        e64[r][3] = pack2f(bb.z, bb.w);
    }

    double L = 0.0;   // meaningful only in tid 32

    for (int t = 0; t < S; t++) {
        // emissions (exp'd) for my row — off-path (warp 0 lanes < 16)
        float eem = 1.0f;
        if (tid < ROWS) eem = __expf(__ldg(&h[(size_t)t * T + r0 + tid]));

        // ---- wait for my own 16B of W_t (canary fast path, safe fallback) ----
        uint4 wv = wait16B(g_W[t & 7] + wslot, (unsigned)NBLK * (unsigned)t);

        ull w64[4];
        w64[0] = pack2u(wv.x << 16, wv.x & 0xffff0000u);
        w64[1] = pack2u(wv.y << 16, wv.y & 0xffff0000u);
        w64[2] = pack2u(wv.z << 16, wv.z & 0xffff0000u);
        w64[3] = pack2u(wv.w << 16, wv.w & 0xffff0000u);
        {   // thread-local max for the off-path normalizer — parity buffer
            float m0 = fmaxf(__uint_as_float(wv.x << 16), __uint_as_float(wv.x & 0xffff0000u));
            float m1 = fmaxf(__uint_as_float(wv.y << 16), __uint_as_float(wv.y & 0xffff0000u));
            float m2 = fmaxf(__uint_as_float(wv.z << 16), __uint_as_float(wv.z & 0xffff0000u));
            float m3 = fmaxf(__uint_as_float(wv.w << 16), __uint_as_float(wv.w & 0xffff0000u));
            mxs[t & 1][tid] = fmaxf(fmaxf(m0, m1), fmaxf(m2, m3));
        }

        // ---- dot: 16 rows x my 8 cols (E in regs) -> v[16] ----
        float v[ROWS];
        #pragma unroll
        for (int r = 0; r < ROWS; r++) {
            ull acc = 0ULL;
            FMA2(acc, e64[r][0], w64[0]);
            FMA2(acc, e64[r][1], w64[1]);
            FMA2(acc, e64[r][2], w64[2]);
            FMA2(acc, e64[r][3], w64[3]);
            float x, y;
            unpack2f(acc, x, y);
            v[r] = x + y;
        }

        // ---- warp split-butterfly: 16 rows over 32 lanes, 16 shuffles ----
        #pragma unroll
        for (int s = 0; s < 4; s++) {
            const int m = 1 << s;
            const int hh = 8 >> s;
            const bool up = (ln & m) != 0;
            #pragma unroll
            for (int i = 0; i < 8; i++) {
                if (i < hh) {
                    float send = up ? v[i] : v[i + hh];
                    float keep = up ? v[i + hh] : v[i];
                    float recv = __shfl_xor_sync(0xffffffffu, send, m);
                    v[i] = keep + recv;
                }
            }
        }
        v[0] += __shfl_xor_sync(0xffffffffu, v[0], 16);
        if (ln < 16) red[t & 1][wid * ROWS + brow] = v[0];

        __syncthreads();   // the ONLY barrier per step

        if (wid == 0) {
            if (ln < ROWS) {
                // ---- finish row ln: sum 8 warp-partials, scale, publish ----
                const float* rb = red[t & 1];
                float rs = ((rb[0 * ROWS + ln] + rb[1 * ROWS + ln]) +
                            (rb[2 * ROWS + ln] + rb[3 * ROWS + ln])) +
                           ((rb[4 * ROWS + ln] + rb[5 * ROWS + ln]) +
                            (rb[6 * ROWS + ln] + rb[7 * ROWS + ln]));
                float n = rs * sNorm[t & 1] * eem;
                unsigned short us = __bfloat16_as_ushort(__float2bfloat16(n));
                unsigned short* dst = (unsigned short*)g_W[(t + 1) & 7] + (r0 + ln);
                asm volatile("st.global.cg.u16 [%0], %1;" :: "l"(dst), "h"(us) : "memory");
            }
            __syncwarp();   // order data stores before the release red
            if (ln == 16) {
                asm volatile("red.release.gpu.global.add.u32 [%0], %1;"
                             :: "l"(&g_cnt), "r"(1u) : "memory");
            } else if (ln == 17) {
                // clear my CTA's 32B in the slot holding W_{t-2}
                unsigned* cz = g_W[(t + 6) & 7] + (r0 >> 1);
                uint4 cv = make_uint4(CANARY, CANARY, CANARY, CANARY);
                asm volatile("st.global.cg.v4.u32 [%0], {%1,%2,%3,%4};"
                             :: "l"(cz), "r"(cv.x), "r"(cv.y), "r"(cv.z), "r"(cv.w) : "memory");
                asm volatile("st.global.cg.v4.u32 [%0], {%1,%2,%3,%4};"
                             :: "l"(cz + 4), "r"(cv.x), "r"(cv.y), "r"(cv.z), "r"(cv.w) : "memory");
            }
        } else if (wid == 1) {
            // ---- warp 1: lagged damped normalizer for step t+1 (off-path) ----
            const float4* m4 = (const float4*)(mxs[t & 1] + ln * 8);
            float4 a = m4[0], b4 = m4[1];
            float m = fmaxf(fmaxf(fmaxf(a.x, a.y), fmaxf(a.z, a.w)),
                            fmaxf(fmaxf(b4.x, b4.y), fmaxf(b4.z, b4.w)));
            #pragma unroll
            for (int off = 16; off; off >>= 1)
                m = fmaxf(m, __shfl_xor_sync(0xffffffffu, m, off));
            if (ln == 0 && t < S - 1) {
                float lr = 0.5f * __logf(m);        // bit-identical in every CTA
                sNorm[(t + 1) & 1] = __expf(-lr);
                L += (double)lr;                    // tid 32
            }
        }
        // No loop-end sync. Free-running warps write only red[(t+1)&1] and
        // mxs[(t+1)&1] before the barrier of t+1, which warps 0/1 join only
        // after their step-t epilogue reads of red[t&1]/mxs[t&1]/sNorm.
        // Reaching step t+2 (same parity) requires passing barrier t+1. Safe.
    }

    if (tid == 32) sL = L;

    // ---- terminal: logZ = log(sum_j W_S[j]*exp(tr[END,j])) + L ----
    if (b == 0) {
        uint4 wv = wait16B(g_W[S & 7] + wslot, (unsigned)NBLK * (unsigned)S);
        const float* te = trans + (size_t)END_IDX * T + c0;
        float p =
            __uint_as_float(wv.x << 16)        * __expf(te[0]) +
            __uint_as_float(wv.x & 0xffff0000u)* __expf(te[1]) +
            __uint_as_float(wv.y << 16)        * __expf(te[2]) +
            __uint_as_float(wv.y & 0xffff0000u)* __expf(te[3]) +
            __uint_as_float(wv.z << 16)        * __expf(te[4]) +
            __uint_as_float(wv.z & 0xffff0000u)* __expf(te[5]) +
            __uint_as_float(wv.w << 16)        * __expf(te[6]) +
            __uint_as_float(wv.w & 0xffff0000u)* __expf(te[7]);
        #pragma unroll
        for (int off = 16; off; off >>= 1)
            p += __shfl_xor_sync(0xffffffffu, p, off);
        __syncthreads();
        if (ln == 0) red[0][wid] = p;
        __syncthreads();
        if (tid == 0) {
            float tot = 0.0f;
            #pragma unroll
            for (int k = 0; k < 8; k++) tot += red[0][k];
            out[0] = __logf(tot) + (float)sL;
        }
    }
}

extern "C" void kernel_launch(void* const* d_in, const int* in_sizes, int n_in,
                              void* d_out, int out_size) {
    const float* h = (const float*)d_in[0];
    const float* trans = (const float*)d_in[1];
    float* out = (float*)d_out;
    int S = in_sizes[0] / T;

    crf_init<<<512, 256>>>(trans);
    crf_main<<<NBLK, NTHR>>>(h, trans, out, S);
}